// round 9
// baseline (speedup 1.0000x reference)
#include <cuda_runtime.h>
#include <cuda_fp16.h>
#include <cstdint>

#define S_LEN 1024
#define B_SZ  64
#define H_DIM 512

// Scratch (allocation-free rule: __device__ globals)
__device__ float  g_lin[(size_t)S_LEN * B_SZ * H_DIM];   // GEMM output / scan input
__device__ __half g_Ahi[(size_t)S_LEN * B_SZ * H_DIM];   // A operand hi (x, then y0)
__device__ __half g_Alo[(size_t)S_LEN * B_SZ * H_DIM];   // A operand lo
__device__ __half g_Whi[2][H_DIM * H_DIM];               // W hi (pre-scaled)
__device__ __half g_Wlo[2][H_DIM * H_DIM];               // W lo (pre-scaled)
__device__ int    g_flags[128];                          // per-4-m-tile done counters

#define W_SCALE     1024.0f
#define W_SCALE_INV (1.0f / 1024.0f)

// ---------------------------------------------------------------------------
// helpers
// ---------------------------------------------------------------------------
__device__ __forceinline__ void mma_f16(float* d,
                                        uint32_t a0, uint32_t a1, uint32_t a2, uint32_t a3,
                                        uint32_t b0, uint32_t b1) {
    asm volatile(
        "mma.sync.aligned.m16n8k16.row.col.f32.f16.f16.f32 "
        "{%0,%1,%2,%3}, {%4,%5,%6,%7}, {%8,%9}, {%0,%1,%2,%3};\n"
        : "+f"(d[0]), "+f"(d[1]), "+f"(d[2]), "+f"(d[3])
        : "r"(a0), "r"(a1), "r"(a2), "r"(a3), "r"(b0), "r"(b1));
}

#define LDSM_X4(r0, r1, r2, r3, addr)                                          \
    asm volatile("ldmatrix.sync.aligned.m8n8.x4.shared.b16 {%0,%1,%2,%3}, [%4];" \
                 : "=r"(r0), "=r"(r1), "=r"(r2), "=r"(r3) : "r"(addr))

__device__ __forceinline__ uint32_t smem_u32(const void* p) {
    uint32_t a;
    asm("{ .reg .u64 t; cvta.to.shared.u64 t, %1; cvt.u32.u64 %0, t; }"
        : "=r"(a) : "l"(p));
    return a;
}

__device__ __forceinline__ void cp_async16(uint32_t dst, const void* src) {
    asm volatile("cp.async.cg.shared.global [%0], [%1], 16;"
                 :: "r"(dst), "l"(src) : "memory");
}

__device__ __forceinline__ uint32_t pack_h2(float a, float b) {
    __half2 h = __floats2half2_rn(a, b);
    return *reinterpret_cast<uint32_t*>(&h);
}

// split (x,y) into packed fp16 hi pair + fp16 lo pair
__device__ __forceinline__ void split2(float x, float y, uint32_t& hi, uint32_t& lo) {
    float hx = __half2float(__float2half_rn(x));
    float hy = __half2float(__float2half_rn(y));
    hi = pack_h2(hx, hy);
    lo = pack_h2(x - hx, y - hy);
}

__device__ __forceinline__ void wait_group(const int* p) {
    int v;
    while (true) {
        asm volatile("ld.acquire.gpu.b32 %0, [%1];" : "=r"(v) : "l"(p) : "memory");
        if (v >= 32) return;
        __nanosleep(128);
    }
}

// compact swizzled stage: A_hi[128x64B] A_lo[...] W_hi[64x64B] W_lo[...]
// swizzle: 16B chunk index ^= (row>>1)&3
#define ST_AHI      0
#define ST_ALO      8192
#define ST_WHI      16384
#define ST_WLO      20480
#define STAGE_BYTES 24576
#define SMEM_DYN    (3 * STAGE_BYTES)   // 73728 B

// ---------------------------------------------------------------------------
// pre-conversion kernels
// ---------------------------------------------------------------------------
__global__ void conv_w_kernel(const float* __restrict__ W,
                              __half* __restrict__ whi, __half* __restrict__ wlo) {
    int i = blockIdx.x * 256 + threadIdx.x;   // over float4; 512*512/4 = 65536
    float4 v = reinterpret_cast<const float4*>(W)[i];
    uint32_t h0, l0, h1, l1;
    split2(v.x * W_SCALE, v.y * W_SCALE, h0, l0);
    split2(v.z * W_SCALE, v.w * W_SCALE, h1, l1);
    reinterpret_cast<uint2*>(whi)[i] = make_uint2(h0, h1);
    reinterpret_cast<uint2*>(wlo)[i] = make_uint2(l0, l1);
}

__global__ void conv_x_kernel(const float* __restrict__ x) {
    size_t i = (size_t)blockIdx.x * 256 + threadIdx.x;  // over float4; 8M
    float4 v = reinterpret_cast<const float4*>(x)[i];
    uint32_t h0, l0, h1, l1;
    split2(v.x, v.y, h0, l0);
    split2(v.z, v.w, h1, l1);
    reinterpret_cast<uint2*>(g_Ahi)[i] = make_uint2(h0, h1);
    reinterpret_cast<uint2*>(g_Alo)[i] = make_uint2(l0, l1);
}

// ---------------------------------------------------------------------------
// Combined per-layer kernel.
// bids [0,64)    : scan role — 4 warps per batch row (H split 4x128, 4/lane)
// bids [64,4160) : GEMM role: C[m][n] = sum_k A[m][k]*W[n][k] + bias[n]
//                  fp16x3, cp.async 3-stage into swizzled smem, ldmatrix feed.
// GEMM tile: BM=128, BN=64, BK=32; 8 warps (4x2), warp tile 32x32, m16n8k16.
// ---------------------------------------------------------------------------
__global__ __launch_bounds__(256, 3) void layer_kernel(
    const __half* __restrict__ whi,
    const __half* __restrict__ wlo,
    const float* __restrict__ bias,
    const float* __restrict__ rec,
    const float* __restrict__ gam,
    const float* __restrict__ bet,
    float* __restrict__ y_ext,
    float* __restrict__ hid,
    int to_y0, int layer)
{
    const int S = S_LEN, B = B_SZ, K = H_DIM, N = H_DIM;
    extern __shared__ __align__(16) char dynsm[];

    if (blockIdx.x >= 64) {
        // =================== GEMM role ===================
        float* C = g_lin;
        uint32_t smb = smem_u32(dynsm);

        int gb = blockIdx.x - 64;
        int nb = gb & 7;            // n fastest -> A-slice reuse in L2
        int mt = gb >> 3;
        int n0 = nb * 64, m0 = mt * 128;

        int tid  = threadIdx.x;
        int warp = tid >> 5, lane = tid & 31;
        int wm = warp & 3, wn = warp >> 2;

        float acc[2][4][4];
#pragma unroll
        for (int mtt = 0; mtt < 2; mtt++)
#pragma unroll
            for (int nt = 0; nt < 4; nt++)
#pragma unroll
                for (int i = 0; i < 4; i++) acc[mtt][nt][i] = 0.0f;

        const __half* Ahi_b = g_Ahi + (size_t)m0 * K;
        const __half* Alo_b = g_Alo + (size_t)m0 * K;
        const __half* Whi_b = whi + (size_t)n0 * K;
        const __half* Wlo_b = wlo + (size_t)n0 * K;

        // per-thread cp.async mapping (swizzled destinations)
        int a_row = tid >> 1;                  // 0..127
        int a_cq0 = (tid & 1) * 2;             // chunk 0/2 (2 chunks per thread)
        int w_row = tid >> 2;                  // 0..63
        int w_cq  = tid & 3;
        uint32_t a_swz = (uint32_t)((a_row >> 1) & 3);
        uint32_t w_swz = (uint32_t)((w_row >> 1) & 3);
        uint32_t a_dst0 = (uint32_t)a_row * 64 + ((((uint32_t)a_cq0    ) ^ a_swz) << 4);
        uint32_t a_dst1 = (uint32_t)a_row * 64 + ((((uint32_t)a_cq0 + 1) ^ a_swz) << 4);
        uint32_t w_dst  = (uint32_t)w_row * 64 + (((uint32_t)w_cq ^ w_swz) << 4);

        // ldmatrix per-lane invariants (verified mapping from R5)
        int aRowIn = (lane & 7) + ((lane >> 3) & 1) * 8;
        uint32_t aKsel = (uint32_t)(lane >> 4);
        uint32_t aRowTerm[2], aSwz[2];
#pragma unroll
        for (int m2 = 0; m2 < 2; m2++) {
            int row = wm * 32 + m2 * 16 + aRowIn;
            aRowTerm[m2] = (uint32_t)row * 64;
            aSwz[m2] = (row >> 1) & 3;
        }
        int bRowIn = (lane & 7) + ((lane >> 4) & 1) * 8;
        uint32_t bKsel = (uint32_t)((lane >> 3) & 1);
        uint32_t bRowTerm[2], bSwz[2];
#pragma unroll
        for (int p = 0; p < 2; p++) {
            int row = wn * 32 + p * 16 + bRowIn;
            bRowTerm[p] = (uint32_t)row * 64;
            bSwz[p] = (row >> 1) & 3;
        }

        auto issue_stage = [&](int sidx, int kt) {
            uint32_t sb = smb + (uint32_t)sidx * STAGE_BYTES;
            size_t srcA = (size_t)a_row * K + kt + a_cq0 * 8;
            cp_async16(sb + ST_AHI + a_dst0, Ahi_b + srcA);
            cp_async16(sb + ST_AHI + a_dst1, Ahi_b + srcA + 8);
            cp_async16(sb + ST_ALO + a_dst0, Alo_b + srcA);
            cp_async16(sb + ST_ALO + a_dst1, Alo_b + srcA + 8);
            size_t srcW = (size_t)w_row * K + kt + w_cq * 8;
            cp_async16(sb + ST_WHI + w_dst, Whi_b + srcW);
            cp_async16(sb + ST_WLO + w_dst, Wlo_b + srcW);
            asm volatile("cp.async.commit_group;" ::: "memory");
        };

        // prologue: stages 0,1
        issue_stage(0, 0);
        issue_stage(1, 32);

        int cur = 0;
        for (int it = 0; it < 16; ++it) {
            if (it < 15) asm volatile("cp.async.wait_group 1;" ::: "memory");
            else         asm volatile("cp.async.wait_group 0;" ::: "memory");
            __syncthreads();   // stage 'it' visible; MMA(it-1) done by all

            if (it < 14) {
                int nxt2 = cur + 2; if (nxt2 >= 3) nxt2 -= 3;
                issue_stage(nxt2, (it + 2) * 32);
            }

            uint32_t sb = smb + (uint32_t)cur * STAGE_BYTES;
#pragma unroll
            for (int kk = 0; kk < 2; kk++) {
                uint32_t ah[2][4], al[2][4], bh[2][4], bl[2][4];
#pragma unroll
                for (int m2 = 0; m2 < 2; m2++) {
                    uint32_t tail = aRowTerm[m2] + ((((uint32_t)kk * 2 + aKsel) ^ aSwz[m2]) << 4);
                    LDSM_X4(ah[m2][0], ah[m2][1], ah[m2][2], ah[m2][3], sb + ST_AHI + tail);
                    LDSM_X4(al[m2][0], al[m2][1], al[m2][2], al[m2][3], sb + ST_ALO + tail);
                }
#pragma unroll
                for (int p = 0; p < 2; p++) {
                    uint32_t tail = bRowTerm[p] + ((((uint32_t)kk * 2 + bKsel) ^ bSwz[p]) << 4);
                    LDSM_X4(bh[p][0], bh[p][1], bh[p][2], bh[p][3], sb + ST_WHI + tail);
                    LDSM_X4(bl[p][0], bl[p][1], bl[p][2], bl[p][3], sb + ST_WLO + tail);
                }
#pragma unroll
                for (int m2 = 0; m2 < 2; m2++) {
#pragma unroll
                    for (int nt = 0; nt < 4; nt++) {
                        int p = nt >> 1, q = nt & 1;
                        uint32_t bf0 = bh[p][2 * q], bf1 = bh[p][2 * q + 1];
                        uint32_t bg0 = bl[p][2 * q], bg1 = bl[p][2 * q + 1];
                        mma_f16(acc[m2][nt], al[m2][0], al[m2][1], al[m2][2], al[m2][3], bf0, bf1);
                        mma_f16(acc[m2][nt], ah[m2][0], ah[m2][1], ah[m2][2], ah[m2][3], bg0, bg1);
                        mma_f16(acc[m2][nt], ah[m2][0], ah[m2][1], ah[m2][2], ah[m2][3], bf0, bf1);
                    }
                }
            }
            cur = cur + 1; if (cur >= 3) cur -= 3;
        }

        // epilogue: unscale, add bias, store (R5-verified column mapping)
        int r = lane >> 2, c = lane & 3;
#pragma unroll
        for (int m2 = 0; m2 < 2; m2++) {
#pragma unroll
            for (int nt = 0; nt < 4; nt++) {
                int row = m0 + wm * 32 + m2 * 16 + r;
                int col = n0 + wn * 32 + (nt >> 1) * 16 + (nt & 1) * 8 + 2 * c;
                float bx = bias[col], by = bias[col + 1];
                *reinterpret_cast<float2*>(C + (size_t)row * N + col) = make_float2(
                    fmaf(acc[m2][nt][0], W_SCALE_INV, bx),
                    fmaf(acc[m2][nt][1], W_SCALE_INV, by));
                *reinterpret_cast<float2*>(C + (size_t)(row + 8) * N + col) = make_float2(
                    fmaf(acc[m2][nt][2], W_SCALE_INV, bx),
                    fmaf(acc[m2][nt][3], W_SCALE_INV, by));
            }
        }

        __syncthreads();
        if (tid == 0) {
            __threadfence();
            atomicAdd(&g_flags[mt >> 2], 1);  // 4 m-tiles x 8 n-blocks = 32
        }
        return;
    }

    // =================== scan role: 4 warps per row ===================
    if (threadIdx.x >= 128) return;

    int b = blockIdx.x;
    int warp = threadIdx.x >> 5, lane = threadIdx.x & 31;
    int c0 = warp * 128 + lane * 4;

    // double-buffered per-warp partials (sum, ssq)
    float2* part = reinterpret_cast<float2*>(dynsm);   // 8 x float2

    float4 rc4 = *reinterpret_cast<const float4*>(rec + c0);
    float4 ga4 = *reinterpret_cast<const float4*>(gam + c0);
    float4 bb4 = *reinterpret_cast<const float4*>(bet + c0);
    float rc[4] = {rc4.x, rc4.y, rc4.z, rc4.w};
    float ga[4] = {ga4.x, ga4.y, ga4.z, ga4.w};
    float bb[4] = {bb4.x, bb4.y, bb4.z, bb4.w};
    float h[4]  = {0.0f, 0.0f, 0.0f, 0.0f};

    const size_t stride = (size_t)B * H_DIM;
    const float*  lp  = g_lin + (size_t)b * H_DIM + c0;
    float*        ypf = to_y0 ? nullptr : (y_ext + (size_t)b * H_DIM + c0);
    __half*       yph = g_Ahi + (size_t)b * H_DIM + c0;
    __half*       ypl = g_Alo + (size_t)b * H_DIM + c0;

    // wait for first tile group, prime depth-2 load pipeline
    wait_group(&g_flags[0]);
    float4 cuA = __ldcg(reinterpret_cast<const float4*>(lp));
    float4 cuB = __ldcg(reinterpret_cast<const float4*>(lp + stride));

#define SCAN_STEP(scur, CU)                                                        \
  {                                                                                \
    h[0] = fmaf(rc[0], h[0], CU.x);                                                \
    h[1] = fmaf(rc[1], h[1], CU.y);                                                \
    h[2] = fmaf(rc[2], h[2], CU.z);                                                \
    h[3] = fmaf(rc[3], h[3], CU.w);                                                \
    {                                                                              \
      int sp = (scur) + 2;                                                         \
      if (sp < S && (sp & 7) == 0) wait_group(&g_flags[sp >> 3]);                  \
      if (sp > S - 1) sp = S - 1;                                                  \
      CU = __ldcg(reinterpret_cast<const float4*>(lp + (size_t)sp * stride));      \
    }                                                                              \
    float sum = (h[0] + h[1]) + (h[2] + h[3]);                                     \
    float ssq = fmaf(h[0], h[0], h[1] * h[1]) + fmaf(h[2], h[2], h[3] * h[3]);     \
    _Pragma("unroll")                                                              \
    for (int off = 16; off >= 1; off >>= 1) {                                      \
      sum += __shfl_xor_sync(0xffffffffu, sum, off);                               \
      ssq += __shfl_xor_sync(0xffffffffu, ssq, off);                               \
    }                                                                              \
    float2* pb = part + (((scur) & 1) << 2);                                       \
    if (lane == 0) pb[warp] = make_float2(sum, ssq);                               \
    asm volatile("bar.sync 3, 128;" ::: "memory");                                 \
    float4 p0 = *reinterpret_cast<float4*>(pb);                                    \
    float4 p1 = *reinterpret_cast<float4*>(pb + 2);                                \
    sum = (p0.x + p0.z) + (p1.x + p1.z);                                           \
    ssq = (p0.y + p0.w) + (p1.y + p1.w);                                           \
    float mean = sum * (1.0f / H_DIM);                                             \
    float var  = fmaf(ssq, 1.0f / H_DIM, -mean * mean);                            \
    float inv  = rsqrtf(var + 1e-6f);                                              \
    _Pragma("unroll")                                                              \
    for (int j = 0; j < 4; j++) {                                                  \
      float o = fmaf((h[j] - mean) * inv, ga[j], bb[j]);                           \
      h[j] = fminf(fmaxf(o, 0.0f), 6.0f);                                          \
    }                                                                              \
    if (to_y0) {                                                                   \
      uint32_t h0, l0, h1, l1;                                                     \
      split2(h[0], h[1], h0, l0);                                                  \
      split2(h[2], h[3], h1, l1);                                                  \
      *reinterpret_cast<uint2*>(yph + (size_t)(scur) * stride) = make_uint2(h0, h1);\
      *reinterpret_cast<uint2*>(ypl + (size_t)(scur) * stride) = make_uint2(l0, l1);\
    } else {                                                                       \
      *reinterpret_cast<float4*>(ypf + (size_t)(scur) * stride) =                  \
          make_float4(h[0], h[1], h[2], h[3]);                                     \
    }                                                                              \
  }

    for (int s = 0; s < S; s += 2) {
        SCAN_STEP(s,     cuA);
        SCAN_STEP(s + 1, cuB);
    }

    // hiddens: ref does cat(dim=-1).view(2,B,H) ->
    // hid[(b>>5)][2*(b&31)+layer][h] = h_last[b][h]
    float* hp = hid + (size_t)(b >> 5) * (B * H_DIM)
                    + (size_t)(2 * (b & 31) + layer) * H_DIM + c0;
    *reinterpret_cast<float4*>(hp) = make_float4(h[0], h[1], h[2], h[3]);
}

// ---------------------------------------------------------------------------
// flag reset (must run before each layer_kernel; graph replays reuse state)
// ---------------------------------------------------------------------------
__global__ void zero_flags_kernel() {
    g_flags[threadIdx.x] = 0;
}

// ---------------------------------------------------------------------------
// launcher
// ---------------------------------------------------------------------------
extern "C" void kernel_launch(void* const* d_in, const int* in_sizes, int n_in,
                              void* d_out, int out_size)
{
    (void)n_in; (void)out_size; (void)in_sizes;
    const float* x    = (const float*)d_in[0];
    const float* W0   = (const float*)d_in[1];
    const float* b0   = (const float*)d_in[2];
    const float* rec0 = (const float*)d_in[3];
    const float* g0   = (const float*)d_in[4];
    const float* be0  = (const float*)d_in[5];
    const float* W1   = (const float*)d_in[6];
    const float* b1   = (const float*)d_in[7];
    const float* rec1 = (const float*)d_in[8];
    const float* g1   = (const float*)d_in[9];
    const float* be1  = (const float*)d_in[10];

    float* out = (float*)d_out;
    float* hid = out + (size_t)S_LEN * B_SZ * H_DIM;

    const int GRID = 64 + (S_LEN * B_SZ / 128) * (H_DIM / 64);  // 64 + 4096

    static bool attr_set = false;
    if (!attr_set) {
        cudaFuncSetAttribute(layer_kernel,
                             cudaFuncAttributeMaxDynamicSharedMemorySize, SMEM_DYN);
        attr_set = true;
    }

    // device symbol addresses (host-side) for W buffers
    __half* whi_dev = nullptr;
    __half* wlo_dev = nullptr;
    cudaGetSymbolAddress((void**)&whi_dev, g_Whi);
    cudaGetSymbolAddress((void**)&wlo_dev, g_Wlo);

    // pre-conversion
    conv_w_kernel<<<H_DIM * H_DIM / 4 / 256, 256>>>(W0, whi_dev, wlo_dev);
    conv_w_kernel<<<H_DIM * H_DIM / 4 / 256, 256>>>(W1, whi_dev + H_DIM * H_DIM,
                                                    wlo_dev + H_DIM * H_DIM);
    conv_x_kernel<<<(int)((size_t)S_LEN * B_SZ * H_DIM / 4 / 256), 256>>>(x);

    // layer 1
    zero_flags_kernel<<<1, 128>>>();
    layer_kernel<<<GRID, 256, SMEM_DYN>>>(whi_dev, wlo_dev, b0, rec0, g0, be0,
                                          nullptr, hid, /*to_y0=*/1, /*layer=*/0);
    // layer 2
    zero_flags_kernel<<<1, 128>>>();
    layer_kernel<<<GRID, 256, SMEM_DYN>>>(whi_dev + H_DIM * H_DIM,
                                          wlo_dev + H_DIM * H_DIM, b1, rec1, g1, be1,
                                          out, hid, /*to_y0=*/0, /*layer=*/1);
}

// round 10
// speedup vs baseline: 1.1853x; 1.1853x over previous
#include <cuda_runtime.h>
#include <cuda_fp16.h>
#include <cstdint>

#define S_LEN 1024
#define B_SZ  64
#define H_DIM 512

// Scratch (allocation-free rule: __device__ globals)
__device__ float  g_lin[(size_t)S_LEN * B_SZ * H_DIM];   // GEMM output / scan input
__device__ __half g_Ahi[(size_t)S_LEN * B_SZ * H_DIM];   // y0 hi (written by scan 1)
__device__ __half g_Alo[(size_t)S_LEN * B_SZ * H_DIM];   // y0 lo
__device__ __half g_Whi[2][H_DIM * H_DIM];               // W hi (pre-scaled)
__device__ __half g_Wlo[2][H_DIM * H_DIM];               // W lo (pre-scaled)
__device__ int    g_flags[2][128];                       // per-layer group counters

#define W_SCALE     1024.0f
#define W_SCALE_INV (1.0f / 1024.0f)

// ---------------------------------------------------------------------------
// helpers
// ---------------------------------------------------------------------------
__device__ __forceinline__ void mma_f16(float* d, const uint32_t* a, const uint32_t* b) {
    asm volatile(
        "mma.sync.aligned.m16n8k16.row.col.f32.f16.f16.f32 "
        "{%0,%1,%2,%3}, {%4,%5,%6,%7}, {%8,%9}, {%0,%1,%2,%3};\n"
        : "+f"(d[0]), "+f"(d[1]), "+f"(d[2]), "+f"(d[3])
        : "r"(a[0]), "r"(a[1]), "r"(a[2]), "r"(a[3]),
          "r"(b[0]), "r"(b[1]));
}

__device__ __forceinline__ uint32_t smem_u32(const void* p) {
    uint32_t a;
    asm("{ .reg .u64 t; cvta.to.shared.u64 t, %1; cvt.u32.u64 %0, t; }"
        : "=r"(a) : "l"(p));
    return a;
}

__device__ __forceinline__ void cp_async16(uint32_t dst, const void* src) {
    asm volatile("cp.async.cg.shared.global [%0], [%1], 16;"
                 :: "r"(dst), "l"(src) : "memory");
}

__device__ __forceinline__ uint32_t pack_h2(float a, float b) {
    __half2 h = __floats2half2_rn(a, b);
    return *reinterpret_cast<uint32_t*>(&h);
}

// split (x,y) into packed fp16 hi pair + fp16 lo pair
__device__ __forceinline__ void split2(float x, float y, uint32_t& hi, uint32_t& lo) {
    float hx = __half2float(__float2half_rn(x));
    float hy = __half2float(__float2half_rn(y));
    hi = pack_h2(hx, hy);
    lo = pack_h2(x - hx, y - hy);
}

__device__ __forceinline__ void wait_group(const int* p) {
    int v;
    while (true) {
        asm volatile("ld.acquire.gpu.b32 %0, [%1];" : "=r"(v) : "l"(p) : "memory");
        if (v >= 32) return;
        __nanosleep(128);
    }
}

// padded stage layout (proven conflict-light with scalar LDS fragments)
struct Stage {
    uint32_t As_hi[128][20];
    uint32_t As_lo[128][20];
    uint32_t Bs_hi[64][20];
    uint32_t Bs_lo[64][20];
};
#define SMEM_L1 (2 * sizeof(Stage))   // 61440 B (double buffer)
#define SMEM_L2 (3 * sizeof(Stage))   // 92160 B (3-stage cp.async)

// ---------------------------------------------------------------------------
// pre-conversion of W (tiny: 2 x 1 MB)
// ---------------------------------------------------------------------------
__global__ void conv_w_kernel(const float* __restrict__ W,
                              __half* __restrict__ whi, __half* __restrict__ wlo) {
    int i = blockIdx.x * 256 + threadIdx.x;   // over float4; 512*512/4 = 65536
    float4 v = reinterpret_cast<const float4*>(W)[i];
    uint32_t h0, l0, h1, l1;
    split2(v.x * W_SCALE, v.y * W_SCALE, h0, l0);
    split2(v.z * W_SCALE, v.w * W_SCALE, h1, l1);
    reinterpret_cast<uint2*>(whi)[i] = make_uint2(h0, h1);
    reinterpret_cast<uint2*>(wlo)[i] = make_uint2(l0, l1);
}

__global__ void zero_flags_kernel() {
    reinterpret_cast<int*>(g_flags)[threadIdx.x] = 0;
}

// ---------------------------------------------------------------------------
// shared GEMM pieces
// ---------------------------------------------------------------------------
__device__ __forceinline__ void gemm_mma_stage(const Stage* cs, float acc[2][4][4],
                                               int wm, int wn, int r, int c) {
#pragma unroll
    for (int kk = 0; kk < 2; kk++) {
        int kb = kk * 8;
        uint32_t ah[2][4], al[2][4], bh[4][2], bl[4][2];
#pragma unroll
        for (int mtt = 0; mtt < 2; mtt++) {
            int row = wm * 32 + mtt * 16 + r;
            ah[mtt][0] = cs->As_hi[row    ][kb + c    ];
            ah[mtt][1] = cs->As_hi[row + 8][kb + c    ];
            ah[mtt][2] = cs->As_hi[row    ][kb + c + 4];
            ah[mtt][3] = cs->As_hi[row + 8][kb + c + 4];
            al[mtt][0] = cs->As_lo[row    ][kb + c    ];
            al[mtt][1] = cs->As_lo[row + 8][kb + c    ];
            al[mtt][2] = cs->As_lo[row    ][kb + c + 4];
            al[mtt][3] = cs->As_lo[row + 8][kb + c + 4];
        }
#pragma unroll
        for (int nt = 0; nt < 4; nt++) {
            int nrow = wn * 32 + nt * 8 + r;
            bh[nt][0] = cs->Bs_hi[nrow][kb + c];
            bh[nt][1] = cs->Bs_hi[nrow][kb + c + 4];
            bl[nt][0] = cs->Bs_lo[nrow][kb + c];
            bl[nt][1] = cs->Bs_lo[nrow][kb + c + 4];
        }
#pragma unroll
        for (int mtt = 0; mtt < 2; mtt++)
#pragma unroll
            for (int nt = 0; nt < 4; nt++) {
                mma_f16(acc[mtt][nt], al[mtt], bh[nt]);  // lo*hi
                mma_f16(acc[mtt][nt], ah[mtt], bl[nt]);  // hi*lo
                mma_f16(acc[mtt][nt], ah[mtt], bh[nt]);  // hi*hi
            }
    }
}

__device__ __forceinline__ void gemm_epilogue(float* C, const float* bias,
                                              float acc[2][4][4],
                                              int m0, int n0, int wm, int wn,
                                              int r, int c) {
#pragma unroll
    for (int mtt = 0; mtt < 2; mtt++) {
#pragma unroll
        for (int nt = 0; nt < 4; nt++) {
            int row = m0 + wm * 32 + mtt * 16 + r;
            int col = n0 + wn * 32 + nt * 8 + 2 * c;
            float bx = bias[col], by = bias[col + 1];
            *reinterpret_cast<float2*>(C + (size_t)row * H_DIM + col) = make_float2(
                fmaf(acc[mtt][nt][0], W_SCALE_INV, bx),
                fmaf(acc[mtt][nt][1], W_SCALE_INV, by));
            *reinterpret_cast<float2*>(C + (size_t)(row + 8) * H_DIM + col) = make_float2(
                fmaf(acc[mtt][nt][2], W_SCALE_INV, bx),
                fmaf(acc[mtt][nt][3], W_SCALE_INV, by));
        }
    }
}

// ---------------------------------------------------------------------------
// scan role: 4 warps per batch row (H split 4x128, 4 elems/lane)
// ---------------------------------------------------------------------------
__device__ __forceinline__ void scan_role(
    const float* __restrict__ rec, const float* __restrict__ gam,
    const float* __restrict__ bet, float* __restrict__ y_ext,
    float* __restrict__ hid, int to_y0, int layer,
    const int* __restrict__ flags, char* dynsm)
{
    const int S = S_LEN, B = B_SZ;
    int b = blockIdx.x;
    int warp = threadIdx.x >> 5, lane = threadIdx.x & 31;
    int c0 = warp * 128 + lane * 4;

    float2* part = reinterpret_cast<float2*>(dynsm);   // 8 x float2 (2 buffers)

    float4 rc4 = *reinterpret_cast<const float4*>(rec + c0);
    float4 ga4 = *reinterpret_cast<const float4*>(gam + c0);
    float4 bb4 = *reinterpret_cast<const float4*>(bet + c0);
    float rc[4] = {rc4.x, rc4.y, rc4.z, rc4.w};
    float ga[4] = {ga4.x, ga4.y, ga4.z, ga4.w};
    float bb[4] = {bb4.x, bb4.y, bb4.z, bb4.w};
    float h[4]  = {0.0f, 0.0f, 0.0f, 0.0f};

    const size_t stride = (size_t)B * H_DIM;
    const float*  lp  = g_lin + (size_t)b * H_DIM + c0;
    float*        ypf = to_y0 ? nullptr : (y_ext + (size_t)b * H_DIM + c0);
    __half*       yph = g_Ahi + (size_t)b * H_DIM + c0;
    __half*       ypl = g_Alo + (size_t)b * H_DIM + c0;

    wait_group(&flags[0]);
    float4 cuA = __ldcg(reinterpret_cast<const float4*>(lp));
    float4 cuB = __ldcg(reinterpret_cast<const float4*>(lp + stride));

#define SCAN_STEP(scur, CU)                                                        \
  {                                                                                \
    h[0] = fmaf(rc[0], h[0], CU.x);                                                \
    h[1] = fmaf(rc[1], h[1], CU.y);                                                \
    h[2] = fmaf(rc[2], h[2], CU.z);                                                \
    h[3] = fmaf(rc[3], h[3], CU.w);                                                \
    {                                                                              \
      int sp = (scur) + 2;                                                         \
      if (sp < S && (sp & 7) == 0) wait_group(&flags[sp >> 3]);                    \
      if (sp > S - 1) sp = S - 1;                                                  \
      CU = __ldcg(reinterpret_cast<const float4*>(lp + (size_t)sp * stride));      \
    }                                                                              \
    float sum = (h[0] + h[1]) + (h[2] + h[3]);                                     \
    float ssq = fmaf(h[0], h[0], h[1] * h[1]) + fmaf(h[2], h[2], h[3] * h[3]);     \
    _Pragma("unroll")                                                              \
    for (int off = 16; off >= 1; off >>= 1) {                                      \
      sum += __shfl_xor_sync(0xffffffffu, sum, off);                               \
      ssq += __shfl_xor_sync(0xffffffffu, ssq, off);                               \
    }                                                                              \
    float2* pb = part + (((scur) & 1) << 2);                                       \
    if (lane == 0) pb[warp] = make_float2(sum, ssq);                               \
    asm volatile("bar.sync 3, 128;" ::: "memory");                                 \
    float4 p0 = *reinterpret_cast<float4*>(pb);                                    \
    float4 p1 = *reinterpret_cast<float4*>(pb + 2);                                \
    sum = (p0.x + p0.z) + (p1.x + p1.z);                                           \
    ssq = (p0.y + p0.w) + (p1.y + p1.w);                                           \
    float mean = sum * (1.0f / H_DIM);                                             \
    float var  = fmaf(ssq, 1.0f / H_DIM, -mean * mean);                            \
    float inv  = rsqrtf(var + 1e-6f);                                              \
    _Pragma("unroll")                                                              \
    for (int j = 0; j < 4; j++) {                                                  \
      float o = fmaf((h[j] - mean) * inv, ga[j], bb[j]);                           \
      h[j] = fminf(fmaxf(o, 0.0f), 6.0f);                                          \
    }                                                                              \
    if (to_y0) {                                                                   \
      uint32_t h0, l0, h1, l1;                                                     \
      split2(h[0], h[1], h0, l0);                                                  \
      split2(h[2], h[3], h1, l1);                                                  \
      *reinterpret_cast<uint2*>(yph + (size_t)(scur) * stride) = make_uint2(h0, h1);\
      *reinterpret_cast<uint2*>(ypl + (size_t)(scur) * stride) = make_uint2(l0, l1);\
    } else {                                                                       \
      *reinterpret_cast<float4*>(ypf + (size_t)(scur) * stride) =                  \
          make_float4(h[0], h[1], h[2], h[3]);                                     \
    }                                                                              \
  }

    for (int s = 0; s < S; s += 2) {
        SCAN_STEP(s,     cuA);
        SCAN_STEP(s + 1, cuB);
    }
#undef SCAN_STEP

    // hiddens: ref does cat(dim=-1).view(2,B,H) ->
    // hid[(b>>5)][2*(b&31)+layer][h] = h_last[b][h]
    float* hp = hid + (size_t)(b >> 5) * (B * H_DIM)
                    + (size_t)(2 * (b & 31) + layer) * H_DIM + c0;
    *reinterpret_cast<float4*>(hp) = make_float4(h[0], h[1], h[2], h[3]);
}

// ---------------------------------------------------------------------------
// LAYER 1: A = x (fp32, inline convert); W pre-split via cp.async.
// 2-stage double buffer, load(it+1) -> MMA(it) -> wait+sync.
// ---------------------------------------------------------------------------
__global__ __launch_bounds__(256, 2) void layer1_kernel(
    const float* __restrict__ x,
    const __half* __restrict__ whi,
    const __half* __restrict__ wlo,
    const float* __restrict__ bias,
    const float* __restrict__ rec,
    const float* __restrict__ gam,
    const float* __restrict__ bet,
    float* __restrict__ hid)
{
    const int K = H_DIM;
    extern __shared__ __align__(16) char dynsm[];

    if (blockIdx.x < 64) {
        if (threadIdx.x >= 128) return;
        scan_role(rec, gam, bet, nullptr, hid, /*to_y0=*/1, /*layer=*/0,
                  g_flags[0], dynsm);
        return;
    }

    // =================== GEMM role ===================
    Stage* stages = reinterpret_cast<Stage*>(dynsm);

    int gb = blockIdx.x - 64;
    int nb = gb & 7;            // n fastest -> A-slice reuse in L2
    int mt = gb >> 3;
    int n0 = nb * 64, m0 = mt * 128;

    int tid  = threadIdx.x;
    int warp = tid >> 5, lane = tid & 31;
    int wm = warp & 3, wn = warp >> 2;
    int r = lane >> 2, c = lane & 3;

    float acc[2][4][4];
#pragma unroll
    for (int mtt = 0; mtt < 2; mtt++)
#pragma unroll
        for (int nt = 0; nt < 4; nt++)
#pragma unroll
            for (int i = 0; i < 4; i++) acc[mtt][nt][i] = 0.0f;

    const float*  Ab    = x + (size_t)m0 * K;
    const __half* Whi_b = whi + (size_t)n0 * K;
    const __half* Wlo_b = wlo + (size_t)n0 * K;

    int w_row = tid >> 2;   // 0..63
    int w_cq  = tid & 3;

    auto load_stage = [&](Stage* st, int kt) {
        // A: 128x32 fp32 = 1024 float4; 4 per thread, inline split
#pragma unroll
        for (int i = 0; i < 4; i++) {
            int idx = tid + i * 256;
            int row = idx >> 3;
            int c4  = idx & 7;
            float4 v = *reinterpret_cast<const float4*>(Ab + (size_t)row * K + kt + c4 * 4);
            uint32_t h0, l0, h1, l1;
            split2(v.x, v.y, h0, l0);
            split2(v.z, v.w, h1, l1);
            st->As_hi[row][c4 * 2] = h0;  st->As_hi[row][c4 * 2 + 1] = h1;
            st->As_lo[row][c4 * 2] = l0;  st->As_lo[row][c4 * 2 + 1] = l1;
        }
        // W: pre-split halves via cp.async (1 hi + 1 lo chunk per thread)
        size_t srcW = (size_t)w_row * K + kt + w_cq * 8;
        cp_async16(smem_u32(&st->Bs_hi[w_row][w_cq * 4]), Whi_b + srcW);
        cp_async16(smem_u32(&st->Bs_lo[w_row][w_cq * 4]), Wlo_b + srcW);
        asm volatile("cp.async.commit_group;" ::: "memory");
    };

    load_stage(&stages[0], 0);
    asm volatile("cp.async.wait_group 0;" ::: "memory");
    __syncthreads();

    int buf = 0;
    for (int it = 0; it < 16; ++it) {
        if (it < 15) load_stage(&stages[buf ^ 1], (it + 1) * 32);
        gemm_mma_stage(&stages[buf], acc, wm, wn, r, c);
        if (it < 15) asm volatile("cp.async.wait_group 0;" ::: "memory");
        __syncthreads();
        buf ^= 1;
    }

    gemm_epilogue(g_lin, bias, acc, m0, n0, wm, wn, r, c);

    __syncthreads();
    if (tid == 0) {
        __threadfence();
        atomicAdd(&g_flags[0][mt >> 2], 1);  // 4 m-tiles x 8 n-blocks = 32
    }
}

// ---------------------------------------------------------------------------
// LAYER 2: A = y0 halves (from scan 1); all operands cp.async, 3-stage.
// ---------------------------------------------------------------------------
__global__ __launch_bounds__(256, 2) void layer2_kernel(
    const __half* __restrict__ whi,
    const __half* __restrict__ wlo,
    const float* __restrict__ bias,
    const float* __restrict__ rec,
    const float* __restrict__ gam,
    const float* __restrict__ bet,
    float* __restrict__ y_out,
    float* __restrict__ hid)
{
    const int K = H_DIM;
    extern __shared__ __align__(16) char dynsm[];

    if (blockIdx.x < 64) {
        if (threadIdx.x >= 128) return;
        scan_role(rec, gam, bet, y_out, hid, /*to_y0=*/0, /*layer=*/1,
                  g_flags[1], dynsm);
        return;
    }

    // =================== GEMM role ===================
    Stage* stages = reinterpret_cast<Stage*>(dynsm);

    int gb = blockIdx.x - 64;
    int nb = gb & 7;
    int mt = gb >> 3;
    int n0 = nb * 64, m0 = mt * 128;

    int tid  = threadIdx.x;
    int warp = tid >> 5, lane = tid & 31;
    int wm = warp & 3, wn = warp >> 2;
    int r = lane >> 2, c = lane & 3;

    float acc[2][4][4];
#pragma unroll
    for (int mtt = 0; mtt < 2; mtt++)
#pragma unroll
        for (int nt = 0; nt < 4; nt++)
#pragma unroll
            for (int i = 0; i < 4; i++) acc[mtt][nt][i] = 0.0f;

    const __half* Ahi_b = g_Ahi + (size_t)m0 * K;
    const __half* Alo_b = g_Alo + (size_t)m0 * K;
    const __half* Whi_b = whi + (size_t)n0 * K;
    const __half* Wlo_b = wlo + (size_t)n0 * K;

    int a_row = tid >> 1;                  // 0..127
    int a_cq0 = (tid & 1) * 2;             // chunk 0/2
    int w_row = tid >> 2;                  // 0..63
    int w_cq  = tid & 3;

    auto issue_stage = [&](Stage* st, int kt) {
#pragma unroll
        for (int i = 0; i < 2; i++) {
            int cq = a_cq0 + i;
            size_t src = (size_t)a_row * K + kt + cq * 8;
            cp_async16(smem_u32(&st->As_hi[a_row][cq * 4]), Ahi_b + src);
            cp_async16(smem_u32(&st->As_lo[a_row][cq * 4]), Alo_b + src);
        }
        size_t srcW = (size_t)w_row * K + kt + w_cq * 8;
        cp_async16(smem_u32(&st->Bs_hi[w_row][w_cq * 4]), Whi_b + srcW);
        cp_async16(smem_u32(&st->Bs_lo[w_row][w_cq * 4]), Wlo_b + srcW);
        asm volatile("cp.async.commit_group;" ::: "memory");
    };

    issue_stage(&stages[0], 0);
    issue_stage(&stages[1], 32);

    int cur = 0;
    for (int it = 0; it < 16; ++it) {
        if (it < 15) asm volatile("cp.async.wait_group 1;" ::: "memory");
        else         asm volatile("cp.async.wait_group 0;" ::: "memory");
        __syncthreads();

        if (it < 14) {
            int nxt2 = cur + 2; if (nxt2 >= 3) nxt2 -= 3;
            issue_stage(&stages[nxt2], (it + 2) * 32);
        }

        gemm_mma_stage(&stages[cur], acc, wm, wn, r, c);
        cur = cur + 1; if (cur >= 3) cur -= 3;
    }

    gemm_epilogue(g_lin, bias, acc, m0, n0, wm, wn, r, c);

    __syncthreads();
    if (tid == 0) {
        __threadfence();
        atomicAdd(&g_flags[1][mt >> 2], 1);
    }
}

// ---------------------------------------------------------------------------
// launcher
// ---------------------------------------------------------------------------
extern "C" void kernel_launch(void* const* d_in, const int* in_sizes, int n_in,
                              void* d_out, int out_size)
{
    (void)n_in; (void)out_size; (void)in_sizes;
    const float* x    = (const float*)d_in[0];
    const float* W0   = (const float*)d_in[1];
    const float* b0   = (const float*)d_in[2];
    const float* rec0 = (const float*)d_in[3];
    const float* g0   = (const float*)d_in[4];
    const float* be0  = (const float*)d_in[5];
    const float* W1   = (const float*)d_in[6];
    const float* b1   = (const float*)d_in[7];
    const float* rec1 = (const float*)d_in[8];
    const float* g1   = (const float*)d_in[9];
    const float* be1  = (const float*)d_in[10];

    float* out = (float*)d_out;
    float* hid = out + (size_t)S_LEN * B_SZ * H_DIM;

    const int GRID = 64 + (S_LEN * B_SZ / 128) * (H_DIM / 64);  // 64 + 4096

    static bool attr_set = false;
    if (!attr_set) {
        cudaFuncSetAttribute(layer1_kernel,
                             cudaFuncAttributeMaxDynamicSharedMemorySize, SMEM_L1);
        cudaFuncSetAttribute(layer2_kernel,
                             cudaFuncAttributeMaxDynamicSharedMemorySize, SMEM_L2);
        attr_set = true;
    }

    __half* whi_dev = nullptr;
    __half* wlo_dev = nullptr;
    cudaGetSymbolAddress((void**)&whi_dev, g_Whi);
    cudaGetSymbolAddress((void**)&wlo_dev, g_Wlo);

    // W pre-split (2 x ~3 us) + flag reset
    conv_w_kernel<<<H_DIM * H_DIM / 4 / 256, 256>>>(W0, whi_dev, wlo_dev);
    conv_w_kernel<<<H_DIM * H_DIM / 4 / 256, 256>>>(W1, whi_dev + H_DIM * H_DIM,
                                                    wlo_dev + H_DIM * H_DIM);
    zero_flags_kernel<<<1, 256>>>();

    layer1_kernel<<<GRID, 256, SMEM_L1>>>(x, whi_dev, wlo_dev, b0,
                                          rec0, g0, be0, hid);
    layer2_kernel<<<GRID, 256, SMEM_L2>>>(whi_dev + H_DIM * H_DIM,
                                          wlo_dev + H_DIM * H_DIM, b1,
                                          rec1, g1, be1, out, hid);
}

// round 12
// speedup vs baseline: 1.1855x; 1.0002x over previous
#include <cuda_runtime.h>
#include <cuda_fp16.h>
#include <cstdint>

#define S_LEN 1024
#define B_SZ  64
#define H_DIM 512

// Scratch (allocation-free rule: __device__ globals)
__device__ float  g_lin[(size_t)S_LEN * B_SZ * H_DIM];   // GEMM output / scan input
__device__ __half g_Ahi[(size_t)S_LEN * B_SZ * H_DIM];   // y0 hi (written by scan 1)
__device__ __half g_Alo[(size_t)S_LEN * B_SZ * H_DIM];   // y0 lo
__device__ __half g_Whi[2][H_DIM * H_DIM];               // W hi (pre-scaled)
__device__ __half g_Wlo[2][H_DIM * H_DIM];               // W lo (pre-scaled)
__device__ int    g_flags[2][128];                       // per-layer group counters

#define W_SCALE     1024.0f
#define W_SCALE_INV (1.0f / 1024.0f)

// ---------------------------------------------------------------------------
// helpers
// ---------------------------------------------------------------------------
__device__ __forceinline__ void mma_f16(float* d,
                                        uint32_t a0, uint32_t a1, uint32_t a2, uint32_t a3,
                                        uint32_t b0, uint32_t b1) {
    asm volatile(
        "mma.sync.aligned.m16n8k16.row.col.f32.f16.f16.f32 "
        "{%0,%1,%2,%3}, {%4,%5,%6,%7}, {%8,%9}, {%0,%1,%2,%3};\n"
        : "+f"(d[0]), "+f"(d[1]), "+f"(d[2]), "+f"(d[3])
        : "r"(a0), "r"(a1), "r"(a2), "r"(a3), "r"(b0), "r"(b1));
}

#define LDSM_X4(r0, r1, r2, r3, addr)                                          \
    asm volatile("ldmatrix.sync.aligned.m8n8.x4.shared.b16 {%0,%1,%2,%3}, [%4];" \
                 : "=r"(r0), "=r"(r1), "=r"(r2), "=r"(r3) : "r"(addr))

__device__ __forceinline__ uint32_t smem_u32(const void* p) {
    uint32_t a;
    asm("{ .reg .u64 t; cvta.to.shared.u64 t, %1; cvt.u32.u64 %0, t; }"
        : "=r"(a) : "l"(p));
    return a;
}

__device__ __forceinline__ void cp_async16(uint32_t dst, const void* src) {
    asm volatile("cp.async.cg.shared.global [%0], [%1], 16;"
                 :: "r"(dst), "l"(src) : "memory");
}

__device__ __forceinline__ uint32_t pack_h2(float a, float b) {
    __half2 h = __floats2half2_rn(a, b);
    return *reinterpret_cast<uint32_t*>(&h);
}

// split (x,y) into packed fp16 hi pair + fp16 lo pair
__device__ __forceinline__ void split2(float x, float y, uint32_t& hi, uint32_t& lo) {
    float hx = __half2float(__float2half_rn(x));
    float hy = __half2float(__float2half_rn(y));
    hi = pack_h2(hx, hy);
    lo = pack_h2(x - hx, y - hy);
}

__device__ __forceinline__ void wait_group(const int* p) {
    int v;
    while (true) {
        asm volatile("ld.acquire.gpu.b32 %0, [%1];" : "=r"(v) : "l"(p) : "memory");
        if (v >= 32) return;
        __nanosleep(128);
    }
}

// compact swizzled stage: rows of 64B, 16B chunk index ^= (row>>1)&3
#define ST_AHI      0
#define ST_ALO      8192
#define ST_WHI      16384
#define ST_WLO      20480
#define STAGE_BYTES 24576
#define SMEM_L1     (2 * STAGE_BYTES)   // 49152 B
#define SMEM_L2     (3 * STAGE_BYTES)   // 73728 B

// ---------------------------------------------------------------------------
// pre-conversion of W (tiny: 2 x 1 MB)
// ---------------------------------------------------------------------------
__global__ void conv_w_kernel(const float* __restrict__ W,
                              __half* __restrict__ whi, __half* __restrict__ wlo) {
    int i = blockIdx.x * 256 + threadIdx.x;   // over float4; 512*512/4 = 65536
    float4 v = reinterpret_cast<const float4*>(W)[i];
    uint32_t h0, l0, h1, l1;
    split2(v.x * W_SCALE, v.y * W_SCALE, h0, l0);
    split2(v.z * W_SCALE, v.w * W_SCALE, h1, l1);
    reinterpret_cast<uint2*>(whi)[i] = make_uint2(h0, h1);
    reinterpret_cast<uint2*>(wlo)[i] = make_uint2(l0, l1);
}

__global__ void zero_flags_kernel() {
    reinterpret_cast<int*>(g_flags)[threadIdx.x] = 0;
}

// ---------------------------------------------------------------------------
// LDSM-fed MMA on one stage (R9-verified addressing) + epilogue
// ---------------------------------------------------------------------------
struct LdsmCtx {
    uint32_t aRowTerm[2], aSwz[2], aKsel;
    uint32_t bRowTerm[2], bSwz[2], bKsel;
};

__device__ __forceinline__ void ldsm_init(LdsmCtx& cx, int wm, int wn, int lane) {
    int aRowIn = (lane & 7) + ((lane >> 3) & 1) * 8;
    cx.aKsel = (uint32_t)(lane >> 4);
#pragma unroll
    for (int m2 = 0; m2 < 2; m2++) {
        int row = wm * 32 + m2 * 16 + aRowIn;
        cx.aRowTerm[m2] = (uint32_t)row * 64;
        cx.aSwz[m2] = (row >> 1) & 3;
    }
    int bRowIn = (lane & 7) + ((lane >> 4) & 1) * 8;
    cx.bKsel = (uint32_t)((lane >> 3) & 1);
#pragma unroll
    for (int p = 0; p < 2; p++) {
        int row = wn * 32 + p * 16 + bRowIn;
        cx.bRowTerm[p] = (uint32_t)row * 64;
        cx.bSwz[p] = (row >> 1) & 3;
    }
}

__device__ __forceinline__ void gemm_mma_stage(uint32_t sb, const LdsmCtx& cx,
                                               float acc[2][4][4]) {
#pragma unroll
    for (int kk = 0; kk < 2; kk++) {
        uint32_t ah[2][4], al[2][4], bh[2][4], bl[2][4];
#pragma unroll
        for (int m2 = 0; m2 < 2; m2++) {
            uint32_t tail = cx.aRowTerm[m2] +
                ((((uint32_t)kk * 2 + cx.aKsel) ^ cx.aSwz[m2]) << 4);
            LDSM_X4(ah[m2][0], ah[m2][1], ah[m2][2], ah[m2][3], sb + ST_AHI + tail);
            LDSM_X4(al[m2][0], al[m2][1], al[m2][2], al[m2][3], sb + ST_ALO + tail);
        }
#pragma unroll
        for (int p = 0; p < 2; p++) {
            uint32_t tail = cx.bRowTerm[p] +
                ((((uint32_t)kk * 2 + cx.bKsel) ^ cx.bSwz[p]) << 4);
            LDSM_X4(bh[p][0], bh[p][1], bh[p][2], bh[p][3], sb + ST_WHI + tail);
            LDSM_X4(bl[p][0], bl[p][1], bl[p][2], bl[p][3], sb + ST_WLO + tail);
        }
#pragma unroll
        for (int m2 = 0; m2 < 2; m2++) {
#pragma unroll
            for (int nt = 0; nt < 4; nt++) {
                int p = nt >> 1, q = nt & 1;
                uint32_t bf0 = bh[p][2 * q], bf1 = bh[p][2 * q + 1];
                uint32_t bg0 = bl[p][2 * q], bg1 = bl[p][2 * q + 1];
                mma_f16(acc[m2][nt], al[m2][0], al[m2][1], al[m2][2], al[m2][3], bf0, bf1);
                mma_f16(acc[m2][nt], ah[m2][0], ah[m2][1], ah[m2][2], ah[m2][3], bg0, bg1);
                mma_f16(acc[m2][nt], ah[m2][0], ah[m2][1], ah[m2][2], ah[m2][3], bf0, bf1);
            }
        }
    }
}

__device__ __forceinline__ void gemm_epilogue(float* C, const float* bias,
                                              float acc[2][4][4],
                                              int m0, int n0, int wm, int wn,
                                              int lane) {
    int r = lane >> 2, c = lane & 3;
#pragma unroll
    for (int m2 = 0; m2 < 2; m2++) {
#pragma unroll
        for (int nt = 0; nt < 4; nt++) {
            int row = m0 + wm * 32 + m2 * 16 + r;
            int col = n0 + wn * 32 + (nt >> 1) * 16 + (nt & 1) * 8 + 2 * c;
            float bx = bias[col], by = bias[col + 1];
            *reinterpret_cast<float2*>(C + (size_t)row * H_DIM + col) = make_float2(
                fmaf(acc[m2][nt][0], W_SCALE_INV, bx),
                fmaf(acc[m2][nt][1], W_SCALE_INV, by));
            *reinterpret_cast<float2*>(C + (size_t)(row + 8) * H_DIM + col) = make_float2(
                fmaf(acc[m2][nt][2], W_SCALE_INV, bx),
                fmaf(acc[m2][nt][3], W_SCALE_INV, by));
        }
    }
}

// ---------------------------------------------------------------------------
// scan role: 4 warps per batch row (H split 4x128, 4 elems/lane)
// ---------------------------------------------------------------------------
__device__ __forceinline__ void scan_role(
    const float* __restrict__ rec, const float* __restrict__ gam,
    const float* __restrict__ bet, float* __restrict__ y_ext,
    float* __restrict__ hid, int to_y0, int layer,
    const int* __restrict__ flags, char* dynsm)
{
    const int S = S_LEN, B = B_SZ;
    int b = blockIdx.x;
    int warp = threadIdx.x >> 5, lane = threadIdx.x & 31;
    int c0 = warp * 128 + lane * 4;

    float2* part = reinterpret_cast<float2*>(dynsm);   // 8 x float2 (2 buffers)

    float4 rc4 = *reinterpret_cast<const float4*>(rec + c0);
    float4 ga4 = *reinterpret_cast<const float4*>(gam + c0);
    float4 bb4 = *reinterpret_cast<const float4*>(bet + c0);
    float rc[4] = {rc4.x, rc4.y, rc4.z, rc4.w};
    float ga[4] = {ga4.x, ga4.y, ga4.z, ga4.w};
    float bb[4] = {bb4.x, bb4.y, bb4.z, bb4.w};
    float h[4]  = {0.0f, 0.0f, 0.0f, 0.0f};

    const size_t stride = (size_t)B * H_DIM;
    const float*  lp  = g_lin + (size_t)b * H_DIM + c0;
    float*        ypf = to_y0 ? nullptr : (y_ext + (size_t)b * H_DIM + c0);
    __half*       yph = g_Ahi + (size_t)b * H_DIM + c0;
    __half*       ypl = g_Alo + (size_t)b * H_DIM + c0;

    wait_group(&flags[0]);
    float4 cuA = __ldcg(reinterpret_cast<const float4*>(lp));
    float4 cuB = __ldcg(reinterpret_cast<const float4*>(lp + stride));

#define SCAN_STEP(scur, CU)                                                        \
  {                                                                                \
    h[0] = fmaf(rc[0], h[0], CU.x);                                                \
    h[1] = fmaf(rc[1], h[1], CU.y);                                                \
    h[2] = fmaf(rc[2], h[2], CU.z);                                                \
    h[3] = fmaf(rc[3], h[3], CU.w);                                                \
    {                                                                              \
      int sp = (scur) + 2;                                                         \
      if (sp < S && (sp & 7) == 0) wait_group(&flags[sp >> 3]);                    \
      if (sp > S - 1) sp = S - 1;                                                  \
      CU = __ldcg(reinterpret_cast<const float4*>(lp + (size_t)sp * stride));      \
    }                                                                              \
    float sum = (h[0] + h[1]) + (h[2] + h[3]);                                     \
    float ssq = fmaf(h[0], h[0], h[1] * h[1]) + fmaf(h[2], h[2], h[3] * h[3]);     \
    _Pragma("unroll")                                                              \
    for (int off = 16; off >= 1; off >>= 1) {                                      \
      sum += __shfl_xor_sync(0xffffffffu, sum, off);                               \
      ssq += __shfl_xor_sync(0xffffffffu, ssq, off);                               \
    }                                                                              \
    float2* pb = part + (((scur) & 1) << 2);                                       \
    if (lane == 0) pb[warp] = make_float2(sum, ssq);                               \
    asm volatile("bar.sync 3, 128;" ::: "memory");                                 \
    float4 p0 = *reinterpret_cast<float4*>(pb);                                    \
    float4 p1 = *reinterpret_cast<float4*>(pb + 2);                                \
    sum = (p0.x + p0.z) + (p1.x + p1.z);                                           \
    ssq = (p0.y + p0.w) + (p1.y + p1.w);                                           \
    float mean = sum * (1.0f / H_DIM);                                             \
    float var  = fmaf(ssq, 1.0f / H_DIM, -mean * mean);                            \
    float inv  = rsqrtf(var + 1e-6f);                                              \
    _Pragma("unroll")                                                              \
    for (int j = 0; j < 4; j++) {                                                  \
      float o = fmaf((h[j] - mean) * inv, ga[j], bb[j]);                           \
      h[j] = fminf(fmaxf(o, 0.0f), 6.0f);                                          \
    }                                                                              \
    if (to_y0) {                                                                   \
      uint32_t h0, l0, h1, l1;                                                     \
      split2(h[0], h[1], h0, l0);                                                  \
      split2(h[2], h[3], h1, l1);                                                  \
      *reinterpret_cast<uint2*>(yph + (size_t)(scur) * stride) = make_uint2(h0, h1);\
      *reinterpret_cast<uint2*>(ypl + (size_t)(scur) * stride) = make_uint2(l0, l1);\
    } else {                                                                       \
      *reinterpret_cast<float4*>(ypf + (size_t)(scur) * stride) =                  \
          make_float4(h[0], h[1], h[2], h[3]);                                     \
    }                                                                              \
  }

    for (int s = 0; s < S; s += 2) {
        SCAN_STEP(s,     cuA);
        SCAN_STEP(s + 1, cuB);
    }
#undef SCAN_STEP

    // hiddens: hid[(b>>5)][2*(b&31)+layer][h] = h_last[b][h]
    float* hp = hid + (size_t)(b >> 5) * (B * H_DIM)
                    + (size_t)(2 * (b & 31) + layer) * H_DIM + c0;
    *reinterpret_cast<float4*>(hp) = make_float4(h[0], h[1], h[2], h[3]);
}

// ---------------------------------------------------------------------------
// LAYER 1: A = x (fp32, inline convert, swizzled STS); W pre-split cp.async.
// 2-stage double buffer, load(it+1) -> MMA(it) -> wait+sync.
// ---------------------------------------------------------------------------
__global__ __launch_bounds__(256, 2) void layer1_kernel(
    const float* __restrict__ x,
    const __half* __restrict__ whi,
    const __half* __restrict__ wlo,
    const float* __restrict__ bias,
    const float* __restrict__ rec,
    const float* __restrict__ gam,
    const float* __restrict__ bet,
    float* __restrict__ hid)
{
    const int K = H_DIM;
    extern __shared__ __align__(16) char dynsm[];

    if (blockIdx.x < 64) {
        if (threadIdx.x >= 128) return;
        scan_role(rec, gam, bet, nullptr, hid, /*to_y0=*/1, /*layer=*/0,
                  g_flags[0], dynsm);
        return;
    }

    // =================== GEMM role ===================
    uint32_t smb = smem_u32(dynsm);

    int gb = blockIdx.x - 64;
    int nb = gb & 7;            // n fastest -> A-slice reuse in L2
    int mt = gb >> 3;
    int n0 = nb * 64, m0 = mt * 128;

    int tid  = threadIdx.x;
    int warp = tid >> 5, lane = tid & 31;
    int wm = warp & 3, wn = warp >> 2;

    float acc[2][4][4];
#pragma unroll
    for (int m2 = 0; m2 < 2; m2++)
#pragma unroll
        for (int nt = 0; nt < 4; nt++)
#pragma unroll
            for (int i = 0; i < 4; i++) acc[m2][nt][i] = 0.0f;

    const float*  Ab    = x + (size_t)m0 * K;
    const __half* Whi_b = whi + (size_t)n0 * K;
    const __half* Wlo_b = wlo + (size_t)n0 * K;

    LdsmCtx cx;
    ldsm_init(cx, wm, wn, lane);

    // A loader: per thread 4 float4 (8 fp32 -> one 8B uint2 per half-chunk)
    // row = idx>>3 (8 float4 per 32-float row), c4 = idx&7
    // swizzled dst: row*64 + (((c4>>1) ^ ((row>>1)&3)) << 4) + (c4&1)*8
    int w_row = tid >> 2;   // 0..63
    int w_cq  = tid & 3;
    uint32_t w_dst = (uint32_t)w_row * 64 +
                     (((uint32_t)w_cq ^ ((uint32_t)(w_row >> 1) & 3)) << 4);

    auto load_stage = [&](int sidx, int kt) {
        uint32_t sb = smb + (uint32_t)sidx * STAGE_BYTES;
#pragma unroll
        for (int i = 0; i < 4; i++) {
            int idx = tid + i * 256;
            int row = idx >> 3;
            int c4  = idx & 7;
            float4 v = *reinterpret_cast<const float4*>(Ab + (size_t)row * K + kt + c4 * 4);
            uint32_t h0, l0, h1, l1;
            split2(v.x, v.y, h0, l0);
            split2(v.z, v.w, h1, l1);
            uint32_t dst = (uint32_t)row * 64 +
                ((((uint32_t)(c4 >> 1)) ^ ((uint32_t)(row >> 1) & 3)) << 4) +
                (uint32_t)(c4 & 1) * 8;
            asm volatile("st.shared.v2.b32 [%0], {%1, %2};"
                         :: "r"(sb + ST_AHI + dst), "r"(h0), "r"(h1) : "memory");
            asm volatile("st.shared.v2.b32 [%0], {%1, %2};"
                         :: "r"(sb + ST_ALO + dst), "r"(l0), "r"(l1) : "memory");
        }
        size_t srcW = (size_t)w_row * K + kt + w_cq * 8;
        cp_async16(sb + ST_WHI + w_dst, Whi_b + srcW);
        cp_async16(sb + ST_WLO + w_dst, Wlo_b + srcW);
        asm volatile("cp.async.commit_group;" ::: "memory");
    };

    load_stage(0, 0);
    asm volatile("cp.async.wait_group 0;" ::: "memory");
    __syncthreads();

    int buf = 0;
    for (int it = 0; it < 16; ++it) {
        if (it < 15) load_stage(buf ^ 1, (it + 1) * 32);
        gemm_mma_stage(smb + (uint32_t)buf * STAGE_BYTES, cx, acc);
        if (it < 15) asm volatile("cp.async.wait_group 0;" ::: "memory");
        __syncthreads();
        buf ^= 1;
    }

    gemm_epilogue(g_lin, bias, acc, m0, n0, wm, wn, lane);

    __syncthreads();
    if (tid == 0) {
        __threadfence();
        atomicAdd(&g_flags[0][mt >> 2], 1);  // 4 m-tiles x 8 n-blocks = 32
    }
}

// ---------------------------------------------------------------------------
// LAYER 2: A = y0 halves (from scan 1); all operands cp.async, 3-stage.
// ---------------------------------------------------------------------------
__global__ __launch_bounds__(256, 2) void layer2_kernel(
    const __half* __restrict__ whi,
    const __half* __restrict__ wlo,
    const float* __restrict__ bias,
    const float* __restrict__ rec,
    const float* __restrict__ gam,
    const float* __restrict__ bet,
    float* __restrict__ y_out,
    float* __restrict__ hid)
{
    const int K = H_DIM;
    extern __shared__ __align__(16) char dynsm[];

    if (blockIdx.x < 64) {
        if (threadIdx.x >= 128) return;
        scan_role(rec, gam, bet, y_out, hid, /*to_y0=*/0, /*layer=*/1,
                  g_flags[1], dynsm);
        return;
    }

    // =================== GEMM role ===================
    uint32_t smb = smem_u32(dynsm);

    int gb = blockIdx.x - 64;
    int nb = gb & 7;
    int mt = gb >> 3;
    int n0 = nb * 64, m0 = mt * 128;

    int tid  = threadIdx.x;
    int warp = tid >> 5, lane = tid & 31;
    int wm = warp & 3, wn = warp >> 2;

    float acc[2][4][4];
#pragma unroll
    for (int m2 = 0; m2 < 2; m2++)
#pragma unroll
        for (int nt = 0; nt < 4; nt++)
#pragma unroll
            for (int i = 0; i < 4; i++) acc[m2][nt][i] = 0.0f;

    const __half* Ahi_b = g_Ahi + (size_t)m0 * K;
    const __half* Alo_b = g_Alo + (size_t)m0 * K;
    const __half* Whi_b = whi + (size_t)n0 * K;
    const __half* Wlo_b = wlo + (size_t)n0 * K;

    LdsmCtx cx;
    ldsm_init(cx, wm, wn, lane);

    int a_row = tid >> 1;                  // 0..127
    int a_cq0 = (tid & 1) * 2;             // chunk 0/2
    int w_row = tid >> 2;                  // 0..63
    int w_cq  = tid & 3;
    uint32_t a_swz = (uint32_t)((a_row >> 1) & 3);
    uint32_t w_swz = (uint32_t)((w_row >> 1) & 3);
    uint32_t a_dst0 = (uint32_t)a_row * 64 + ((((uint32_t)a_cq0    ) ^ a_swz) << 4);
    uint32_t a_dst1 = (uint32_t)a_row * 64 + ((((uint32_t)a_cq0 + 1) ^ a_swz) << 4);
    uint32_t w_dst  = (uint32_t)w_row * 64 + (((uint32_t)w_cq ^ w_swz) << 4);

    auto issue_stage = [&](int sidx, int kt) {
        uint32_t sb = smb + (uint32_t)sidx * STAGE_BYTES;
        size_t srcA = (size_t)a_row * K + kt + a_cq0 * 8;
        cp_async16(sb + ST_AHI + a_dst0, Ahi_b + srcA);
        cp_async16(sb + ST_AHI + a_dst1, Ahi_b + srcA + 8);
        cp_async16(sb + ST_ALO + a_dst0, Alo_b + srcA);
        cp_async16(sb + ST_ALO + a_dst1, Alo_b + srcA + 8);
        size_t srcW = (size_t)w_row * K + kt + w_cq * 8;
        cp_async16(sb + ST_WHI + w_dst, Whi_b + srcW);
        cp_async16(sb + ST_WLO + w_dst, Wlo_b + srcW);
        asm volatile("cp.async.commit_group;" ::: "memory");
    };

    issue_stage(0, 0);
    issue_stage(1, 32);

    int cur = 0;
    for (int it = 0; it < 16; ++it) {
        if (it < 15) asm volatile("cp.async.wait_group 1;" ::: "memory");
        else         asm volatile("cp.async.wait_group 0;" ::: "memory");
        __syncthreads();

        if (it < 14) {
            int nxt2 = cur + 2; if (nxt2 >= 3) nxt2 -= 3;
            issue_stage(nxt2, (it + 2) * 32);
        }

        gemm_mma_stage(smb + (uint32_t)cur * STAGE_BYTES, cx, acc);
        cur = cur + 1; if (cur >= 3) cur -= 3;
    }

    gemm_epilogue(g_lin, bias, acc, m0, n0, wm, wn, lane);

    __syncthreads();
    if (tid == 0) {
        __threadfence();
        atomicAdd(&g_flags[1][mt >> 2], 1);
    }
}

// ---------------------------------------------------------------------------
// launcher
// ---------------------------------------------------------------------------
extern "C" void kernel_launch(void* const* d_in, const int* in_sizes, int n_in,
                              void* d_out, int out_size)
{
    (void)n_in; (void)out_size; (void)in_sizes;
    const float* x    = (const float*)d_in[0];
    const float* W0   = (const float*)d_in[1];
    const float* b0   = (const float*)d_in[2];
    const float* rec0 = (const float*)d_in[3];
    const float* g0   = (const float*)d_in[4];
    const float* be0  = (const float*)d_in[5];
    const float* W1   = (const float*)d_in[6];
    const float* b1   = (const float*)d_in[7];
    const float* rec1 = (const float*)d_in[8];
    const float* g1   = (const float*)d_in[9];
    const float* be1  = (const float*)d_in[10];

    float* out = (float*)d_out;
    float* hid = out + (size_t)S_LEN * B_SZ * H_DIM;

    const int GRID = 64 + (S_LEN * B_SZ / 128) * (H_DIM / 64);  // 64 + 4096

    static bool attr_set = false;
    if (!attr_set) {
        cudaFuncSetAttribute(layer1_kernel,
                             cudaFuncAttributeMaxDynamicSharedMemorySize, SMEM_L1);
        cudaFuncSetAttribute(layer2_kernel,
                             cudaFuncAttributeMaxDynamicSharedMemorySize, SMEM_L2);
        attr_set = true;
    }

    __half* whi_dev = nullptr;
    __half* wlo_dev = nullptr;
    cudaGetSymbolAddress((void**)&whi_dev, g_Whi);
    cudaGetSymbolAddress((void**)&wlo_dev, g_Wlo);

    // W pre-split (2 x ~3 us) + flag reset
    conv_w_kernel<<<H_DIM * H_DIM / 4 / 256, 256>>>(W0, whi_dev, wlo_dev);
    conv_w_kernel<<<H_DIM * H_DIM / 4 / 256, 256>>>(W1, whi_dev + H_DIM * H_DIM,
                                                    wlo_dev + H_DIM * H_DIM);
    zero_flags_kernel<<<1, 256>>>();

    layer1_kernel<<<GRID, 256, SMEM_L1>>>(x, whi_dev, wlo_dev, b0,
                                          rec0, g0, be0, hid);
    layer2_kernel<<<GRID, 256, SMEM_L2>>>(whi_dev + H_DIM * H_DIM,
                                          wlo_dev + H_DIM * H_DIM, b1,
                                          rec1, g1, be1, out, hid);
}